// round 1
// baseline (speedup 1.0000x reference)
#include <cuda_runtime.h>

// RROIAlign: features (2,256,200,200) f32, rois (512,6) f32 -> out (512,256,7,7) f32
// OUT 7x7, spatial_scale 0.25, sample_num 2 (2x2 samples per bin, mean).
//
// Strategy: block <-> exactly one roi slice. Per roi there are 49*4 = 196
// (bin, sample) descriptors, identical across all 256 channels. 12544 outputs
// per roi = 49 blocks x 256 threads, so blockIdx.x/49 = roi id. First 196
// threads compute descriptors (base offset + 4 bilinear weights with validity
// and 1/4 mean folded in) into shared memory; then all threads gather.

#define FC 256
#define FH 200
#define FW 200
#define OUT_HW 49          // 7*7
#define NSAMP 4            // 2x2
#define NDESC 196          // 49*4
#define PER_ROI 12544      // 256*49

__global__ void __launch_bounds__(256, 8) rroi_align_kernel(
    const float* __restrict__ feat,
    const float* __restrict__ rois,
    float* __restrict__ out)
{
    __shared__ int   s_base[NDESC];
    __shared__ float s_w00[NDESC];
    __shared__ float s_w01[NDESC];
    __shared__ float s_w10[NDESC];
    __shared__ float s_w11[NDESC];

    const int tid = threadIdx.x;
    const int blk = blockIdx.x;
    const int n   = blk / 49;       // roi index
    const int j   = blk % 49;       // slice within roi

    if (tid < NDESC) {
        const float* r = rois + n * 6;
        const int   b  = (int)r[0];
        const float cx = r[1] * 0.25f;
        const float cy = r[2] * 0.25f;
        const float rw = fmaxf(r[3] * 0.25f, 1.0f);
        const float rh = fmaxf(r[4] * 0.25f, 1.0f);
        const float theta = r[5];
        const float bin_w = rw * (1.0f / 7.0f);
        const float bin_h = rh * (1.0f / 7.0f);
        float st, ct;
        __sincosf(theta, &st, &ct);

        const int p  = tid >> 2;        // bin 0..48
        const int s  = tid & 3;         // sample 0..3
        const int ph = p / 7;
        const int pw = p - ph * 7;
        const int sh = s >> 1;          // frac index for y
        const int sw = s & 1;           // frac index for x
        const float fh = ((float)sh + 0.5f) * 0.5f;   // 0.25 / 0.75
        const float fw = ((float)sw + 0.5f) * 0.5f;

        const float yy = -rh * 0.5f + ((float)ph + fh) * bin_h;
        const float xx = -rw * 0.5f + ((float)pw + fw) * bin_w;

        float x = xx * ct + yy * st + cx;
        float y = yy * ct - xx * st + cy;

        const bool valid = (y > -1.0f) && (y < (float)FH) &&
                           (x > -1.0f) && (x < (float)FW);

        y = fminf(fmaxf(y, 0.0f), (float)(FH - 1));
        x = fminf(fmaxf(x, 0.0f), (float)(FW - 1));

        const float y0f = fminf(floorf(y), (float)(FH - 2));
        const float x0f = fminf(floorf(x), (float)(FW - 2));
        const int y0 = (int)y0f;
        const int x0 = (int)x0f;

        const float ly = y - y0f;
        const float lx = x - x0f;
        const float hy = 1.0f - ly;
        const float hx = 1.0f - lx;
        const float m  = valid ? 0.25f : 0.0f;   // fold sample mean + validity

        s_base[tid] = b * (FC * FH * FW) + y0 * FW + x0;
        s_w00[tid]  = hy * hx * m;
        s_w01[tid]  = hy * lx * m;
        s_w10[tid]  = ly * hx * m;
        s_w11[tid]  = ly * lx * m;
    }
    __syncthreads();

    const int rem  = j * 256 + tid;        // 0..12543 within this roi
    const int c    = rem / 49;
    const int p    = rem - c * 49;
    const int coff = c * (FH * FW);

    float acc = 0.0f;
#pragma unroll
    for (int s = 0; s < 4; ++s) {
        const int   di   = p * 4 + s;
        const int   base = s_base[di] + coff;
        const float w00  = s_w00[di];
        const float w01  = s_w01[di];
        const float w10  = s_w10[di];
        const float w11  = s_w11[di];
        acc += w00 * __ldg(feat + base)
             + w01 * __ldg(feat + base + 1)
             + w10 * __ldg(feat + base + FW)
             + w11 * __ldg(feat + base + FW + 1);
    }

    out[n * PER_ROI + rem] = acc;
}

extern "C" void kernel_launch(void* const* d_in, const int* in_sizes, int n_in,
                              void* d_out, int out_size)
{
    const float* feat = (const float*)d_in[0];   // (2,256,200,200)
    const float* rois = (const float*)d_in[1];   // (512,6)
    float* out = (float*)d_out;                  // (512,256,7,7)

    const int n_rois = in_sizes[1] / 6;          // 512
    rroi_align_kernel<<<n_rois * 49, 256>>>(feat, rois, out);
}

// round 2
// speedup vs baseline: 1.0993x; 1.0993x over previous
#include <cuda_runtime.h>

// RROIAlign: features (2,256,200,200) f32, rois (512,6) f32 -> out (512,256,7,7) f32
// spatial_scale 0.25, 2x2 samples per bin, mean.
//
// Design: warp <-> 2x4 bin patch; lane <-> (bin, sample) descriptor held in
// REGISTERS (no smem in hot loop). 8 warps cover the 7x7 grid padded to 8x8
// (invalid lanes predicated off). Warp loops over its channel range; the 4
// sample lanes of each bin are reduced with 2 shuffles; lane s==0 stores.
// Lane clustering = adjacent samples -> fewer L1 wavefronts per LDG.

#define FC 256
#define FH 200
#define FW 200
#define PLANE 40000        // FH*FW
#define PER_ROI 12544      // FC*49
#define CSPLIT 4
#define CPB 64             // channels per block (FC / CSPLIT)

__global__ void __launch_bounds__(256) rroi_align_kernel(
    const float* __restrict__ feat,
    const float* __restrict__ rois,
    float* __restrict__ out)
{
    const int n     = blockIdx.x >> 2;            // roi index
    const int cs    = (blockIdx.x & 3) * CPB;     // channel start
    const int lane  = threadIdx.x & 31;
    const int chunk = threadIdx.x >> 5;           // 0..7: which 2x4 bin patch

    // lane -> (bin-in-patch, sample)
    const int s  = lane & 3;                      // sample 0..3
    const int bl = lane >> 2;                     // bin-in-patch 0..7
    const int pw = ((chunk & 3) << 1) + (bl & 1); // 0..7 (7 invalid)
    const int ph = ((chunk >> 2) << 2) + (bl >> 1); // 0..7 (7 invalid)
    const bool lv = (pw < 7) && (ph < 7);

    // ---- per-lane descriptor (registers) ----
    const float* r = rois + n * 6;
    const int   b  = (int)r[0];
    const float cx = r[1] * 0.25f;
    const float cy = r[2] * 0.25f;
    const float rw = fmaxf(r[3] * 0.25f, 1.0f);
    const float rh = fmaxf(r[4] * 0.25f, 1.0f);
    float st, ct;
    __sincosf(r[5], &st, &ct);

    const float bin_w = rw * (1.0f / 7.0f);
    const float bin_h = rh * (1.0f / 7.0f);
    const float fh = ((float)(s >> 1) + 0.5f) * 0.5f;  // 0.25 / 0.75
    const float fw = ((float)(s & 1)  + 0.5f) * 0.5f;

    const float yy = -rh * 0.5f + ((float)ph + fh) * bin_h;
    const float xx = -rw * 0.5f + ((float)pw + fw) * bin_w;

    float x = xx * ct + yy * st + cx;
    float y = yy * ct - xx * st + cy;

    const bool valid = (y > -1.0f) && (y < (float)FH) &&
                       (x > -1.0f) && (x < (float)FW);

    y = fminf(fmaxf(y, 0.0f), (float)(FH - 1));
    x = fminf(fmaxf(x, 0.0f), (float)(FW - 1));

    const float y0f = fminf(floorf(y), (float)(FH - 2));
    const float x0f = fminf(floorf(x), (float)(FW - 2));

    const float ly = y - y0f;
    const float lx = x - x0f;
    const float hy = 1.0f - ly;
    const float hx = 1.0f - lx;
    const float m  = (valid && lv) ? 0.25f : 0.0f;   // fold mean + validity

    const float w00 = hy * hx * m;
    const float w01 = hy * lx * m;
    const float w10 = ly * hx * m;
    const float w11 = ly * lx * m;

    // base pointer for this lane's sample (channel 0 of this block's range)
    const float* f0 = feat + (size_t)b * (FC * PLANE)
                    + (size_t)(cs) * PLANE
                    + (int)y0f * FW + (int)x0f;

    float* op = out + n * PER_ROI + cs * 49 + ph * 7 + pw;

    // ---- hot loop over channels ----
#pragma unroll 4
    for (int c = 0; c < CPB; ++c) {
        const float* fc = f0 + c * PLANE;
        float v = 0.0f;
        if (lv) {
            v = w00 * __ldg(fc)
              + w01 * __ldg(fc + 1)
              + w10 * __ldg(fc + FW)
              + w11 * __ldg(fc + FW + 1);
        }
        // reduce the 4 sample lanes of each bin
        v += __shfl_down_sync(0xFFFFFFFFu, v, 1);
        v += __shfl_down_sync(0xFFFFFFFFu, v, 2);
        if (lv && s == 0) op[c * 49] = v;
    }
}

extern "C" void kernel_launch(void* const* d_in, const int* in_sizes, int n_in,
                              void* d_out, int out_size)
{
    const float* feat = (const float*)d_in[0];   // (2,256,200,200)
    const float* rois = (const float*)d_in[1];   // (512,6)
    float* out = (float*)d_out;                  // (512,256,7,7)

    const int n_rois = in_sizes[1] / 6;          // 512
    rroi_align_kernel<<<n_rois * CSPLIT, 256>>>(feat, rois, out);
}

// round 3
// speedup vs baseline: 1.8573x; 1.6895x over previous
#include <cuda_runtime.h>

// RROIAlign via NHWC re-layout.
// Kernel 1: transpose features (2,256,200,200) NCHW -> NHWC scratch (2,200,200,256).
// Kernel 2: gather. In NHWC one bilinear corner for all 256 channels is a
//           contiguous, 1KB-aligned vector -> perfectly coalesced LDG.128.
//           Block = (roi, 128-channel half); lane = channel quad; 8 bins in
//           flight per iteration; per-bin float4 accumulators staged in smem,
//           final store coalesced.

#define FB 2
#define FC 256
#define FH 200
#define FW 200
#define PER_ROI 12544      // 256*49

__device__ float g_nhwc[(size_t)FB * FH * FW * FC];   // 81.92 MB scratch

// ---------------- transpose NCHW -> NHWC ----------------
__global__ void __launch_bounds__(256) transpose_kernel(const float* __restrict__ feat)
{
    __shared__ float tile[32][33];
    const int tx = threadIdx.x;            // 0..31
    const int ty = threadIdx.y;            // 0..7
    const int w0 = blockIdx.x * 32;        // 7 tiles cover W=200
    const int h  = blockIdx.y;             // 0..199
    const int z  = blockIdx.z;             // b*8 + ctile
    const int b  = z >> 3;
    const int c0 = (z & 7) * 32;

#pragma unroll
    for (int k = 0; k < 4; ++k) {
        const int c = c0 + ty + 8 * k;
        const int w = w0 + tx;
        if (w < FW)
            tile[ty + 8 * k][tx] = feat[(((size_t)b * FC + c) * FH + h) * FW + w];
    }
    __syncthreads();
#pragma unroll
    for (int k = 0; k < 4; ++k) {
        const int w = w0 + ty + 8 * k;
        const int c = c0 + tx;
        if (w < FW)
            g_nhwc[(((size_t)b * FH + h) * FW + w) * FC + c] = tile[tx][ty + 8 * k];
    }
}

// ---------------- gather ----------------
__global__ void __launch_bounds__(256) gather_kernel(
    const float* __restrict__ rois,
    float* __restrict__ out)
{
    __shared__ int    s_base[196];
    __shared__ float4 s_w[196];
    __shared__ float4 s_acc[49][33];       // [bin][quad], padded

    const int n   = blockIdx.x >> 1;           // roi
    const int ch0 = (blockIdx.x & 1) * 128;    // channel half
    const int tid = threadIdx.x;

    // ---- 196 (bin, sample) descriptors in smem ----
    if (tid < 196) {
        const float* r = rois + n * 6;
        const int   b  = (int)r[0];
        const float cx = r[1] * 0.25f;
        const float cy = r[2] * 0.25f;
        const float rw = fmaxf(r[3] * 0.25f, 1.0f);
        const float rh = fmaxf(r[4] * 0.25f, 1.0f);
        float st, ct;
        __sincosf(r[5], &st, &ct);

        const float bin_w = rw * (1.0f / 7.0f);
        const float bin_h = rh * (1.0f / 7.0f);

        const int p  = tid >> 2;        // bin 0..48
        const int s  = tid & 3;         // sample 0..3
        const int ph = p / 7;
        const int pw = p - ph * 7;
        const float fh = ((float)(s >> 1) + 0.5f) * 0.5f;
        const float fw = ((float)(s & 1)  + 0.5f) * 0.5f;

        const float yy = -rh * 0.5f + ((float)ph + fh) * bin_h;
        const float xx = -rw * 0.5f + ((float)pw + fw) * bin_w;

        float x = xx * ct + yy * st + cx;
        float y = yy * ct - xx * st + cy;

        const bool valid = (y > -1.0f) && (y < (float)FH) &&
                           (x > -1.0f) && (x < (float)FW);

        y = fminf(fmaxf(y, 0.0f), (float)(FH - 1));
        x = fminf(fmaxf(x, 0.0f), (float)(FW - 1));

        const float y0f = fminf(floorf(y), (float)(FH - 2));
        const float x0f = fminf(floorf(x), (float)(FW - 2));

        const float ly = y - y0f;
        const float lx = x - x0f;
        const float hy = 1.0f - ly;
        const float hx = 1.0f - lx;
        const float m  = valid ? 0.25f : 0.0f;

        s_base[tid] = ((b * FH + (int)y0f) * FW + (int)x0f) * FC + ch0;
        s_w[tid] = make_float4(hy * hx * m, hy * lx * m, ly * hx * m, ly * lx * m);
    }
    __syncthreads();

    const int q = tid & 31;        // channel quad: ch0 + 4q .. +3
    const int g = tid >> 5;        // bin group 0..7

#pragma unroll
    for (int it = 0; it < 7; ++it) {
        const int bin = it * 8 + g;
        if (bin < 49) {
            const int d4 = bin * 4;
            float4 acc = make_float4(0.f, 0.f, 0.f, 0.f);
#pragma unroll
            for (int s = 0; s < 4; ++s) {
                const int    base = s_base[d4 + s] + 4 * q;
                const float4 w    = s_w[d4 + s];
                const float4 a  = *(const float4*)(g_nhwc + base);
                const float4 b2 = *(const float4*)(g_nhwc + base + FC);
                const float4 c2 = *(const float4*)(g_nhwc + base + FW * FC);
                const float4 d2 = *(const float4*)(g_nhwc + base + FW * FC + FC);
                acc.x += w.x * a.x + w.y * b2.x + w.z * c2.x + w.w * d2.x;
                acc.y += w.x * a.y + w.y * b2.y + w.z * c2.y + w.w * d2.y;
                acc.z += w.x * a.z + w.y * b2.z + w.z * c2.z + w.w * d2.z;
                acc.w += w.x * a.w + w.y * b2.w + w.z * c2.w + w.w * d2.w;
            }
            s_acc[bin][q] = acc;
        }
    }
    __syncthreads();

    // ---- coalesced writeout: out[n][ch0+c][bin] ----
    float* ob = out + n * PER_ROI + ch0 * 49;
    const float* sa = (const float*)s_acc;
#pragma unroll
    for (int i = tid; i < 128 * 49; i += 256) {
        const int c  = i / 49;
        const int bn = i - c * 49;
        ob[i] = sa[(bn * 33 + (c >> 2)) * 4 + (c & 3)];
    }
}

extern "C" void kernel_launch(void* const* d_in, const int* in_sizes, int n_in,
                              void* d_out, int out_size)
{
    const float* feat = (const float*)d_in[0];   // (2,256,200,200)
    const float* rois = (const float*)d_in[1];   // (512,6)
    float* out = (float*)d_out;                  // (512,256,7,7)

    const int n_rois = in_sizes[1] / 6;          // 512

    transpose_kernel<<<dim3(7, FH, FB * 8), dim3(32, 8)>>>(feat);
    gather_kernel<<<n_rois * 2, 256>>>(rois, out);
}

// round 4
// speedup vs baseline: 2.6020x; 1.4009x over previous
#include <cuda_runtime.h>
#include <cuda_fp16.h>

// RROIAlign via fp16-NHWC re-layout.
// Kernel 1: NCHW f32 (2,256,200,200) -> NHWC half scratch (2,200,200,256).
// Kernel 2: gather; one bilinear corner for 128 channels = 256B contiguous
//           -> coalesced LDG.64 per lane (4 channels). fp32 accumulation.
// Halving scratch precision halves L2 gather traffic (the measured limiter).

#define FB 2
#define FC 256
#define FH 200
#define FW 200
#define PER_ROI 12544      // 256*49

__device__ __half g_h[(size_t)FB * FH * FW * FC];   // 41 MB scratch

// ---------------- transpose NCHW f32 -> NHWC half ----------------
// grid (7 wtiles, 200 h, 2b*4 ctiles), block (32,8). Tile: 64 ch x 32 w.
__global__ void __launch_bounds__(256) transpose_kernel(const float* __restrict__ feat)
{
    __shared__ float tile[64][33];
    const int tx = threadIdx.x;            // 0..31
    const int ty = threadIdx.y;            // 0..7
    const int w0 = blockIdx.x * 32;
    const int h  = blockIdx.y;
    const int z  = blockIdx.z;             // b*4 + ctile
    const int b  = z >> 2;
    const int c0 = (z & 3) * 64;

    // load: warp = fixed channel, coalesced along w
#pragma unroll
    for (int k = 0; k < 8; ++k) {
        const int c = c0 + ty + 8 * k;
        const int w = w0 + tx;
        if (w < FW)
            tile[ty + 8 * k][tx] = feat[(((size_t)b * FC + c) * FH + h) * FW + w];
    }
    __syncthreads();

    // store: warp = fixed w, lanes = half2 along channels (128B/warp)
#pragma unroll
    for (int k = 0; k < 4; ++k) {
        const int wl = ty + 8 * k;
        const int w  = w0 + wl;
        if (w < FW) {
            const __half2 v = __floats2half2_rn(tile[2 * tx][wl], tile[2 * tx + 1][wl]);
            *(__half2*)(g_h + (((size_t)b * FH + h) * FW + w) * FC + c0 + 2 * tx) = v;
        }
    }
}

// ---------------- gather ----------------
__global__ void __launch_bounds__(256) gather_kernel(
    const float* __restrict__ rois,
    float* __restrict__ out)
{
    __shared__ int    s_base[196];
    __shared__ float4 s_w[196];
    __shared__ float4 s_acc[49][33];       // [bin][quad], padded

    const int n   = blockIdx.x >> 1;           // roi
    const int ch0 = (blockIdx.x & 1) * 128;    // channel half
    const int tid = threadIdx.x;

    if (tid < 196) {
        const float* r = rois + n * 6;
        const int   b  = (int)r[0];
        const float cx = r[1] * 0.25f;
        const float cy = r[2] * 0.25f;
        const float rw = fmaxf(r[3] * 0.25f, 1.0f);
        const float rh = fmaxf(r[4] * 0.25f, 1.0f);
        float st, ct;
        __sincosf(r[5], &st, &ct);

        const float bin_w = rw * (1.0f / 7.0f);
        const float bin_h = rh * (1.0f / 7.0f);

        const int p  = tid >> 2;        // bin 0..48
        const int s  = tid & 3;         // sample 0..3
        const int ph = p / 7;
        const int pw = p - ph * 7;
        const float fh = ((float)(s >> 1) + 0.5f) * 0.5f;
        const float fw = ((float)(s & 1)  + 0.5f) * 0.5f;

        const float yy = -rh * 0.5f + ((float)ph + fh) * bin_h;
        const float xx = -rw * 0.5f + ((float)pw + fw) * bin_w;

        float x = xx * ct + yy * st + cx;
        float y = yy * ct - xx * st + cy;

        const bool valid = (y > -1.0f) && (y < (float)FH) &&
                           (x > -1.0f) && (x < (float)FW);

        y = fminf(fmaxf(y, 0.0f), (float)(FH - 1));
        x = fminf(fmaxf(x, 0.0f), (float)(FW - 1));

        const float y0f = fminf(floorf(y), (float)(FH - 2));
        const float x0f = fminf(floorf(x), (float)(FW - 2));

        const float ly = y - y0f;
        const float lx = x - x0f;
        const float hy = 1.0f - ly;
        const float hx = 1.0f - lx;
        const float m  = valid ? 0.25f : 0.0f;

        s_base[tid] = ((b * FH + (int)y0f) * FW + (int)x0f) * FC + ch0;
        s_w[tid] = make_float4(hy * hx * m, hy * lx * m, ly * hx * m, ly * lx * m);
    }
    __syncthreads();

    const int q = tid & 31;        // channel quad: ch0 + 4q .. +3
    const int g = tid >> 5;        // bin group 0..7

#pragma unroll
    for (int it = 0; it < 7; ++it) {
        const int bin = it * 8 + g;
        if (bin < 49) {
            const int d4 = bin * 4;
            float4 acc = make_float4(0.f, 0.f, 0.f, 0.f);
#pragma unroll
            for (int s = 0; s < 4; ++s) {
                const int    base = s_base[d4 + s] + 4 * q;
                const float4 w    = s_w[d4 + s];
                const __half2* pa = (const __half2*)(g_h + base);
                const __half2* pb = (const __half2*)(g_h + base + FC);
                const __half2* pc = (const __half2*)(g_h + base + FW * FC);
                const __half2* pd = (const __half2*)(g_h + base + FW * FC + FC);
                const float2 a0 = __half22float2(pa[0]);
                const float2 a1 = __half22float2(pa[1]);
                const float2 b0 = __half22float2(pb[0]);
                const float2 b1 = __half22float2(pb[1]);
                const float2 c0_ = __half22float2(pc[0]);
                const float2 c1 = __half22float2(pc[1]);
                const float2 d0 = __half22float2(pd[0]);
                const float2 d1 = __half22float2(pd[1]);
                acc.x += w.x * a0.x + w.y * b0.x + w.z * c0_.x + w.w * d0.x;
                acc.y += w.x * a0.y + w.y * b0.y + w.z * c0_.y + w.w * d0.y;
                acc.z += w.x * a1.x + w.y * b1.x + w.z * c1.x + w.w * d1.x;
                acc.w += w.x * a1.y + w.y * b1.y + w.z * c1.y + w.w * d1.y;
            }
            s_acc[bin][q] = acc;
        }
    }
    __syncthreads();

    // coalesced writeout: out[n][ch0+c][bin]
    float* ob = out + n * PER_ROI + ch0 * 49;
    const float* sa = (const float*)s_acc;
#pragma unroll
    for (int i = tid; i < 128 * 49; i += 256) {
        const int c  = i / 49;
        const int bn = i - c * 49;
        ob[i] = sa[(bn * 33 + (c >> 2)) * 4 + (c & 3)];
    }
}

extern "C" void kernel_launch(void* const* d_in, const int* in_sizes, int n_in,
                              void* d_out, int out_size)
{
    const float* feat = (const float*)d_in[0];   // (2,256,200,200)
    const float* rois = (const float*)d_in[1];   // (512,6)
    float* out = (float*)d_out;                  // (512,256,7,7)

    const int n_rois = in_sizes[1] / 6;          // 512

    transpose_kernel<<<dim3(7, FH, FB * 4), dim3(32, 8)>>>(feat);
    gather_kernel<<<n_rois * 2, 256>>>(rois, out);
}

// round 5
// speedup vs baseline: 2.9021x; 1.1153x over previous
#include <cuda_runtime.h>
#include <cuda_fp16.h>

// RROIAlign via fp16-NHWC re-layout.
// K1: NCHW f32 -> NHWC half, half2 packed at load time, conflict-free smem.
// K2: gather; lane = 8-channel group (LDG.128 per corner), block = (roi,
//     64-channel quarter) -> 2048 blocks, ~18KB smem, 2 bin-iterations.
//     fp32 accumulation; staged in smem for coalesced writeout.

#define FB 2
#define FC 256
#define FH 200
#define FW 200
#define PER_ROI 12544      // 256*49

__device__ __half g_h[(size_t)FB * FH * FW * FC];   // 41 MB scratch

// ---------------- transpose NCHW f32 -> NHWC half ----------------
// grid (7 wtiles, 200 h, 2b*4 ctiles), block (32,8). Tile: 64 ch x 32 w.
__global__ void __launch_bounds__(256) transpose_kernel(const float* __restrict__ feat)
{
    __shared__ unsigned tile2[32][33];     // [w][cpair]
    const int tx = threadIdx.x;            // 0..31
    const int ty = threadIdx.y;            // 0..7
    const int w0 = blockIdx.x * 32;
    const int h  = blockIdx.y;
    const int z  = blockIdx.z;             // b*4 + ctile
    const int b  = z >> 2;
    const int c0 = (z & 3) * 64;

    const int w = w0 + tx;
#pragma unroll
    for (int k = 0; k < 4; ++k) {
        const int cp = ty + 8 * k;                 // channel pair 0..31
        const int c  = c0 + 2 * cp;
        if (w < FW) {
            const float f0 = feat[(((size_t)b * FC + c)     * FH + h) * FW + w];
            const float f1 = feat[(((size_t)b * FC + c + 1) * FH + h) * FW + w];
            const __half2 v = __floats2half2_rn(f0, f1);
            tile2[tx][cp] = *(const unsigned*)&v;
        }
    }
    __syncthreads();
#pragma unroll
    for (int k = 0; k < 4; ++k) {
        const int wl = ty + 8 * k;
        const int w2 = w0 + wl;
        if (w2 < FW)
            ((unsigned*)g_h)[(((size_t)b * FH + h) * FW + w2) * (FC / 2) + c0 / 2 + tx]
                = tile2[wl][tx];
    }
}

// ---------------- gather ----------------
__global__ void __launch_bounds__(256) gather_kernel(
    const float* __restrict__ rois,
    float* __restrict__ out)
{
    __shared__ int    s_base[196];
    __shared__ float4 s_w[196];
    __shared__ float  s_acc[49][8][9];     // [bin][q8][8 ch + pad]

    const int n   = blockIdx.x >> 2;           // roi
    const int ch0 = (blockIdx.x & 3) * 64;     // channel quarter
    const int tid = threadIdx.x;

    if (tid < 196) {
        const float* r = rois + n * 6;
        const int   b  = (int)r[0];
        const float cx = r[1] * 0.25f;
        const float cy = r[2] * 0.25f;
        const float rw = fmaxf(r[3] * 0.25f, 1.0f);
        const float rh = fmaxf(r[4] * 0.25f, 1.0f);
        float st, ct;
        __sincosf(r[5], &st, &ct);

        const float bin_w = rw * (1.0f / 7.0f);
        const float bin_h = rh * (1.0f / 7.0f);

        const int p  = tid >> 2;        // bin 0..48
        const int s  = tid & 3;         // sample 0..3
        const int ph = p / 7;
        const int pw = p - ph * 7;
        const float fh = ((float)(s >> 1) + 0.5f) * 0.5f;
        const float fw = ((float)(s & 1)  + 0.5f) * 0.5f;

        const float yy = -rh * 0.5f + ((float)ph + fh) * bin_h;
        const float xx = -rw * 0.5f + ((float)pw + fw) * bin_w;

        float x = xx * ct + yy * st + cx;
        float y = yy * ct - xx * st + cy;

        const bool valid = (y > -1.0f) && (y < (float)FH) &&
                           (x > -1.0f) && (x < (float)FW);

        y = fminf(fmaxf(y, 0.0f), (float)(FH - 1));
        x = fminf(fmaxf(x, 0.0f), (float)(FW - 1));

        const float y0f = fminf(floorf(y), (float)(FH - 2));
        const float x0f = fminf(floorf(x), (float)(FW - 2));

        const float ly = y - y0f;
        const float lx = x - x0f;
        const float hy = 1.0f - ly;
        const float hx = 1.0f - lx;
        const float m  = valid ? 0.25f : 0.0f;

        s_base[tid] = ((b * FH + (int)y0f) * FW + (int)x0f) * FC + ch0;
        s_w[tid] = make_float4(hy * hx * m, hy * lx * m, ly * hx * m, ly * lx * m);
    }
    __syncthreads();

    const int q8  = tid & 7;            // 8-channel group
    const int sub = (tid >> 3) & 3;     // bin sub-index within warp
    const int wid = tid >> 5;           // warp id 0..7

#pragma unroll
    for (int it = 0; it < 2; ++it) {
        const int bin = it * 32 + wid * 4 + sub;   // 0..63
        if (bin < 49) {
            const int d4 = bin * 4;
            float acc[8] = {0.f, 0.f, 0.f, 0.f, 0.f, 0.f, 0.f, 0.f};
#pragma unroll
            for (int s = 0; s < 4; ++s) {
                const int    base = s_base[d4 + s] + 8 * q8;
                const float4 wgt  = s_w[d4 + s];
                const uint4 ra = *(const uint4*)(g_h + base);
                const uint4 rb = *(const uint4*)(g_h + base + FC);
                const uint4 rc = *(const uint4*)(g_h + base + FW * FC);
                const uint4 rd = *(const uint4*)(g_h + base + FW * FC + FC);
                const unsigned* pa = &ra.x;
                const unsigned* pb = &rb.x;
                const unsigned* pc = &rc.x;
                const unsigned* pd = &rd.x;
#pragma unroll
                for (int j = 0; j < 4; ++j) {
                    const float2 fa = __half22float2(*(const __half2*)&pa[j]);
                    const float2 fb = __half22float2(*(const __half2*)&pb[j]);
                    const float2 fc = __half22float2(*(const __half2*)&pc[j]);
                    const float2 fd = __half22float2(*(const __half2*)&pd[j]);
                    acc[2*j]   += wgt.x * fa.x + wgt.y * fb.x + wgt.z * fc.x + wgt.w * fd.x;
                    acc[2*j+1] += wgt.x * fa.y + wgt.y * fb.y + wgt.z * fc.y + wgt.w * fd.y;
                }
            }
#pragma unroll
            for (int j = 0; j < 8; ++j)
                s_acc[bin][q8][j] = acc[j];
        }
    }
    __syncthreads();

    // coalesced writeout: out[n][ch0+c][bin]
    float* ob = out + n * PER_ROI + ch0 * 49;
    const float* sa = &s_acc[0][0][0];
#pragma unroll
    for (int i = tid; i < 64 * 49; i += 256) {
        const int c  = i / 49;
        const int bn = i - c * 49;
        ob[i] = sa[bn * 72 + (c >> 3) * 9 + (c & 7)];
    }
}

extern "C" void kernel_launch(void* const* d_in, const int* in_sizes, int n_in,
                              void* d_out, int out_size)
{
    const float* feat = (const float*)d_in[0];   // (2,256,200,200)
    const float* rois = (const float*)d_in[1];   // (512,6)
    float* out = (float*)d_out;                  // (512,256,7,7)

    const int n_rois = in_sizes[1] / 6;          // 512

    transpose_kernel<<<dim3(7, FH, FB * 4), dim3(32, 8)>>>(feat);
    gather_kernel<<<n_rois * 4, 256>>>(rois, out);
}

// round 6
// speedup vs baseline: 2.9266x; 1.0084x over previous
#include <cuda_runtime.h>
#include <cuda_fp16.h>

// RROIAlign via fp16-NHWC re-layout.
// K1: NCHW f32 -> NHWC half (near DRAM floor).
// K2: gather; lane = 8-channel group (LDG.128/corner); bilinear combine in
//     HFMA2 with half2-broadcast weights from smem; per-sample fp32
//     accumulate. __launch_bounds__(256,6) for 6 blocks/SM occupancy.

#define FB 2
#define FC 256
#define FH 200
#define FW 200
#define PER_ROI 12544      // 256*49

__device__ __half g_h[(size_t)FB * FH * FW * FC];   // 41 MB scratch

static __device__ __forceinline__ __half2 u2h(unsigned u) {
    __half2 h;
    *reinterpret_cast<unsigned*>(&h) = u;
    return h;
}

// ---------------- transpose NCHW f32 -> NHWC half ----------------
__global__ void __launch_bounds__(256) transpose_kernel(const float* __restrict__ feat)
{
    __shared__ unsigned tile2[32][33];     // [w][cpair]
    const int tx = threadIdx.x;
    const int ty = threadIdx.y;
    const int w0 = blockIdx.x * 32;
    const int h  = blockIdx.y;
    const int z  = blockIdx.z;             // b*4 + ctile
    const int b  = z >> 2;
    const int c0 = (z & 3) * 64;

    const int w = w0 + tx;
#pragma unroll
    for (int k = 0; k < 4; ++k) {
        const int cp = ty + 8 * k;
        const int c  = c0 + 2 * cp;
        if (w < FW) {
            const float f0 = feat[(((size_t)b * FC + c)     * FH + h) * FW + w];
            const float f1 = feat[(((size_t)b * FC + c + 1) * FH + h) * FW + w];
            const __half2 v = __floats2half2_rn(f0, f1);
            tile2[tx][cp] = *(const unsigned*)&v;
        }
    }
    __syncthreads();
#pragma unroll
    for (int k = 0; k < 4; ++k) {
        const int wl = ty + 8 * k;
        const int w2 = w0 + wl;
        if (w2 < FW)
            ((unsigned*)g_h)[(((size_t)b * FH + h) * FW + w2) * (FC / 2) + c0 / 2 + tx]
                = tile2[wl][tx];
    }
}

// ---------------- gather ----------------
__global__ void __launch_bounds__(256, 6) gather_kernel(
    const float* __restrict__ rois,
    float* __restrict__ out)
{
    __shared__ int   s_base[196];
    __shared__ uint4 s_wh[196];            // 4x half2-broadcast weights
    __shared__ float s_acc[49][8][9];      // [bin][q8][8 ch + pad]

    const int n   = blockIdx.x >> 2;           // roi
    const int ch0 = (blockIdx.x & 3) * 64;     // channel quarter
    const int tid = threadIdx.x;

    if (tid < 196) {
        const float* r = rois + n * 6;
        const int   b  = (int)r[0];
        const float cx = r[1] * 0.25f;
        const float cy = r[2] * 0.25f;
        const float rw = fmaxf(r[3] * 0.25f, 1.0f);
        const float rh = fmaxf(r[4] * 0.25f, 1.0f);
        float st, ct;
        __sincosf(r[5], &st, &ct);

        const float bin_w = rw * (1.0f / 7.0f);
        const float bin_h = rh * (1.0f / 7.0f);

        const int p  = tid >> 2;        // bin 0..48
        const int s  = tid & 3;         // sample 0..3
        const int ph = p / 7;
        const int pw = p - ph * 7;
        const float fh = ((float)(s >> 1) + 0.5f) * 0.5f;
        const float fw = ((float)(s & 1)  + 0.5f) * 0.5f;

        const float yy = -rh * 0.5f + ((float)ph + fh) * bin_h;
        const float xx = -rw * 0.5f + ((float)pw + fw) * bin_w;

        float x = xx * ct + yy * st + cx;
        float y = yy * ct - xx * st + cy;

        const bool valid = (y > -1.0f) && (y < (float)FH) &&
                           (x > -1.0f) && (x < (float)FW);

        y = fminf(fmaxf(y, 0.0f), (float)(FH - 1));
        x = fminf(fmaxf(x, 0.0f), (float)(FW - 1));

        const float y0f = fminf(floorf(y), (float)(FH - 2));
        const float x0f = fminf(floorf(x), (float)(FW - 2));

        const float ly = y - y0f;
        const float lx = x - x0f;
        const float hy = 1.0f - ly;
        const float hx = 1.0f - lx;
        const float m  = valid ? 0.25f : 0.0f;

        s_base[tid] = ((b * FH + (int)y0f) * FW + (int)x0f) * FC + ch0;

        const __half2 h00 = __float2half2_rn(hy * hx * m);
        const __half2 h01 = __float2half2_rn(hy * lx * m);
        const __half2 h10 = __float2half2_rn(ly * hx * m);
        const __half2 h11 = __float2half2_rn(ly * lx * m);
        uint4 wq;
        wq.x = *(const unsigned*)&h00;
        wq.y = *(const unsigned*)&h01;
        wq.z = *(const unsigned*)&h10;
        wq.w = *(const unsigned*)&h11;
        s_wh[tid] = wq;
    }
    __syncthreads();

    const int q8  = tid & 7;            // 8-channel group
    const int sub = (tid >> 3) & 3;     // bin sub-index within warp
    const int wid = tid >> 5;           // warp id 0..7

#pragma unroll
    for (int it = 0; it < 2; ++it) {
        const int bin = it * 32 + wid * 4 + sub;   // 0..63
        if (bin < 49) {
            const int d4 = bin * 4;
            float acc[8] = {0.f, 0.f, 0.f, 0.f, 0.f, 0.f, 0.f, 0.f};
#pragma unroll
            for (int s = 0; s < 4; ++s) {
                const int   base = s_base[d4 + s] + 8 * q8;
                const uint4 wq   = s_wh[d4 + s];
                const __half2 wa = u2h(wq.x);
                const __half2 wb = u2h(wq.y);
                const __half2 wc = u2h(wq.z);
                const __half2 wd = u2h(wq.w);

                const uint4 ra = __ldg((const uint4*)(g_h + base));
                const uint4 rb = __ldg((const uint4*)(g_h + base + FC));
                const uint4 rc = __ldg((const uint4*)(g_h + base + FW * FC));
                const uint4 rd = __ldg((const uint4*)(g_h + base + FW * FC + FC));
                const unsigned* pa = &ra.x;
                const unsigned* pb = &rb.x;
                const unsigned* pc = &rc.x;
                const unsigned* pd = &rd.x;
#pragma unroll
                for (int j = 0; j < 4; ++j) {
                    __half2 t = __hmul2(wa, u2h(pa[j]));
                    t = __hfma2(wb, u2h(pb[j]), t);
                    t = __hfma2(wc, u2h(pc[j]), t);
                    t = __hfma2(wd, u2h(pd[j]), t);
                    const float2 f = __half22float2(t);
                    acc[2 * j]     += f.x;
                    acc[2 * j + 1] += f.y;
                }
            }
#pragma unroll
            for (int j = 0; j < 8; ++j)
                s_acc[bin][q8][j] = acc[j];
        }
    }
    __syncthreads();

    // coalesced writeout: out[n][ch0+c][bin]
    float* ob = out + n * PER_ROI + ch0 * 49;
    const float* sa = &s_acc[0][0][0];
#pragma unroll
    for (int i = tid; i < 64 * 49; i += 256) {
        const int c  = i / 49;
        const int bn = i - c * 49;
        ob[i] = sa[bn * 72 + (c >> 3) * 9 + (c & 7)];
    }
}

extern "C" void kernel_launch(void* const* d_in, const int* in_sizes, int n_in,
                              void* d_out, int out_size)
{
    const float* feat = (const float*)d_in[0];   // (2,256,200,200)
    const float* rois = (const float*)d_in[1];   // (512,6)
    float* out = (float*)d_out;                  // (512,256,7,7)

    const int n_rois = in_sizes[1] / 6;          // 512

    transpose_kernel<<<dim3(7, FH, FB * 4), dim3(32, 8)>>>(feat);
    gather_kernel<<<n_rois * 4, 256>>>(rois, out);
}